// round 11
// baseline (speedup 1.0000x reference)
#include <cuda_runtime.h>

// Causal FIR: y[row][t] = sum_{k=0}^{15} b[k] * x[row][t-k], zero init.
// x: [64, 480000] f32, b: [16] f32, y: [64, 480000] f32.
// R8: warp-chunked mapping. Each warp = 256 contiguous outputs as 2 chunks
// of 128; lane l does 4 contiguous outputs per chunk -> every LDG.128/
// STG.128 is warp-contiguous (4 wf/instr, full sectors): 0.1875 wf/output
// (R7's coalescing) at R6's thread count (8 outputs/thread, low per-thread
// overhead). Taps in __constant__ -> LDCU/uniform regs (regs ~30).

#define N_TAPS 16
#define T_LEN 480000
#define BATCH 64
#define CHUNK 128            // outputs per warp-chunk (4 per lane)
#define CHUNKS 2             // chunks per warp -> 8 outputs/thread

__constant__ float c_taps[N_TAPS];

__global__ __launch_bounds__(256) void fir_kernel(
    const float* __restrict__ x,
    float* __restrict__ y)
{
    const int row  = blockIdx.y;
    const int lane = threadIdx.x & 31;
    const int gwarp = (blockIdx.x * blockDim.x + threadIdx.x) >> 5;
    const int warp_base = gwarp * (CHUNK * CHUNKS);

    const float* __restrict__ xr = x + (size_t)row * T_LEN;
    float* __restrict__ yr = y + (size_t)row * T_LEN;

    #pragma unroll
    for (int c = 0; c < CHUNKS; c++) {
        const int t0 = warp_base + c * CHUNK + lane * 4;
        if (t0 < T_LEN) {
            // v[i] = x[t0 - 16 + i], i in [0, 20). t0 % 4 == 0 -> 16B-aligned;
            // warp-contiguous lane stride 16B -> fully coalesced, MLP=5.
            float v[20];
            if (t0 >= N_TAPS) {
                const float4* __restrict__ p =
                    reinterpret_cast<const float4*>(xr + t0 - 16);
                #pragma unroll
                for (int i = 0; i < 5; i++) {
                    float4 f = p[i];
                    v[4*i + 0] = f.x;
                    v[4*i + 1] = f.y;
                    v[4*i + 2] = f.z;
                    v[4*i + 3] = f.w;
                }
            } else {
                // Row head (lanes 0-3 of warp 0, chunk 0): zero-padded.
                #pragma unroll
                for (int i = 0; i < 20; i++) {
                    int idx = t0 - 16 + i;
                    v[i] = (idx >= 0) ? xr[idx] : 0.0f;
                }
            }

            // y[t0+j] = sum_k c_taps[k] * v[16 + j - k]; taps via LDCU.
            float a0 = 0.0f, a1 = 0.0f, a2 = 0.0f, a3 = 0.0f;
            #pragma unroll
            for (int k = 0; k < N_TAPS; k++) {
                const float t = c_taps[k];
                a0 = fmaf(t, v[16 + 0 - k], a0);
                a1 = fmaf(t, v[16 + 1 - k], a1);
                a2 = fmaf(t, v[16 + 2 - k], a2);
                a3 = fmaf(t, v[16 + 3 - k], a3);
            }

            float4 o;
            o.x = a0; o.y = a1; o.z = a2; o.w = a3;
            *reinterpret_cast<float4*>(yr + t0) = o;
        }
    }
}

extern "C" void kernel_launch(void* const* d_in, const int* in_sizes, int n_in,
                              void* d_out, int out_size)
{
    const float* x = (const float*)d_in[0];
    const float* b = (const float*)d_in[1];
    float* y = (float*)d_out;

    // Taps -> constant bank (64 B D2D async copy; graph-capturable).
    cudaMemcpyToSymbolAsync(c_taps, b, N_TAPS * sizeof(float), 0,
                            cudaMemcpyDeviceToDevice, 0);

    const int threads = 256;                         // 8 warps/block
    const int outputs_per_block = 8 * CHUNK * CHUNKS;  // 2048
    dim3 grid((T_LEN + outputs_per_block - 1) / outputs_per_block, BATCH); // (235, 64)
    fir_kernel<<<grid, threads>>>(x, y);
}

// round 13
// speedup vs baseline: 1.0081x; 1.0081x over previous
#include <cuda_runtime.h>

// Causal FIR: y[row][t] = sum_{k=0}^{15} b[k] * x[row][t-k], zero init.
// x: [64, 480000] f32, b: [16] f32, y: [64, 480000] f32.
// R11: smem tile staging. Every global float is loaded exactly once,
// fully coalesced (2 LDG.128/thread + 16-float block halo); the
// halo-replicated reads move to the smem crossbar (~17us of capacity vs
// 35us kernel -> free). L1tex instrs per 8 outputs: 8 -> 4. Compute phase
// uses lane-4-contiguous chunks: 16B lane stride in smem = conflict-free
// LDS.128, and coalesced STG.128. Taps via __constant__ (LDCU, uniform
// regs). DRAM should finally bind (~35us floor).

#define N_TAPS 16
#define T_LEN 480000
#define BATCH 64
#define TILE 2048
#define THREADS 256

__constant__ float c_taps[N_TAPS];

__global__ __launch_bounds__(THREADS) void fir_kernel(
    const float* __restrict__ x,
    float* __restrict__ y)
{
    __shared__ float s[N_TAPS + TILE];   // s[i] = x[tile_base - 16 + i]

    const int row       = blockIdx.y;
    const int tile_base = blockIdx.x * TILE;
    const int tid       = threadIdx.x;

    const float* __restrict__ xr = x + (size_t)row * T_LEN;
    float* __restrict__ yr       = y + (size_t)row * T_LEN;

    // ---- Load phase: tile loaded once, fully coalesced ----
    #pragma unroll
    for (int i = 0; i < TILE / (THREADS * 4); i++) {      // 2 iters
        const int off = (tid + i * THREADS) * 4;          // 0..2044, 16B-aligned
        const int g   = tile_base + off;
        float4 f = make_float4(0.f, 0.f, 0.f, 0.f);
        if (g < T_LEN)                                    // T_LEN % 4 == 0
            f = *reinterpret_cast<const float4*>(xr + g);
        *reinterpret_cast<float4*>(&s[N_TAPS + off]) = f;
    }
    // Halo: 16 floats before the tile (zeros at row start).
    if (tid < 4) {
        const int g = tile_base - 16 + tid * 4;
        float4 f = make_float4(0.f, 0.f, 0.f, 0.f);
        if (g >= 0)
            f = *reinterpret_cast<const float4*>(xr + g);
        *reinterpret_cast<float4*>(&s[tid * 4]) = f;
    }
    __syncthreads();

    // ---- Compute phase: conflict-free smem reads, coalesced stores ----
    const int warp = tid >> 5;
    const int lane = tid & 31;

    #pragma unroll
    for (int c = 0; c < 2; c++) {
        const int local = warp * 256 + c * 128 + lane * 4;  // pos in tile
        const int t0    = tile_base + local;
        if (t0 < T_LEN) {
            // v[i] = s[local + i] = x[t0 - 16 + i]; 5 conflict-free LDS.128.
            float v[20];
            const float4* p = reinterpret_cast<const float4*>(&s[local]);
            #pragma unroll
            for (int i = 0; i < 5; i++) {
                float4 f = p[i];
                v[4*i + 0] = f.x;
                v[4*i + 1] = f.y;
                v[4*i + 2] = f.z;
                v[4*i + 3] = f.w;
            }

            float a0 = 0.f, a1 = 0.f, a2 = 0.f, a3 = 0.f;
            #pragma unroll
            for (int k = 0; k < N_TAPS; k++) {
                const float t = c_taps[k];
                a0 = fmaf(t, v[16 + 0 - k], a0);
                a1 = fmaf(t, v[16 + 1 - k], a1);
                a2 = fmaf(t, v[16 + 2 - k], a2);
                a3 = fmaf(t, v[16 + 3 - k], a3);
            }

            float4 o;
            o.x = a0; o.y = a1; o.z = a2; o.w = a3;
            *reinterpret_cast<float4*>(yr + t0) = o;
        }
    }
}

extern "C" void kernel_launch(void* const* d_in, const int* in_sizes, int n_in,
                              void* d_out, int out_size)
{
    const float* x = (const float*)d_in[0];
    const float* b = (const float*)d_in[1];
    float* y = (float*)d_out;

    // Taps -> constant bank (64 B D2D async copy; graph-capturable).
    cudaMemcpyToSymbolAsync(c_taps, b, N_TAPS * sizeof(float), 0,
                            cudaMemcpyDeviceToDevice, 0);

    dim3 grid((T_LEN + TILE - 1) / TILE, BATCH);   // (235, 64)
    fir_kernel<<<grid, THREADS>>>(x, y);
}

// round 17
// speedup vs baseline: 1.0942x; 1.0854x over previous
#include <cuda_runtime.h>

// Causal FIR: y[row][t] = sum_{k=0}^{15} b[k] * x[row][t-k], zero init.
// x: [64, 480000] f32, b: [16] f32, y: [64, 480000] f32.
// R13: R6 champion body (OUTS=8, __constant__ taps) + ONE change:
// y stores are streaming (__stcs -> STG.CS, evict-first). x is 122.9MB vs
// ~126MB L2 -- it nearly fits. Normal write-allocate y stores were evicting
// x every replay; evict-first stores let x stay L2-resident across graph
// replays, cutting DRAM traffic ~195MB -> ~130-150MB at the observed
// ~5.1TB/s DRAM ceiling. (ncu flushes caches; judge by bench dur_us.)

#define N_TAPS 16
#define T_LEN 480000
#define BATCH 64
#define OUTS_PER_THREAD 8

__constant__ float c_taps[N_TAPS];

__global__ __launch_bounds__(256) void fir_kernel(
    const float* __restrict__ x,
    float* __restrict__ y)
{
    const int row = blockIdx.y;
    const int t0  = (blockIdx.x * blockDim.x + threadIdx.x) * OUTS_PER_THREAD;
    if (t0 >= T_LEN) return;

    const float* __restrict__ xr = x + (size_t)row * T_LEN;

    // v[i] = x[t0 - 16 + i], i in [0, 24). t0 % 8 == 0 so xr + t0 - 16 is
    // 32B-aligned: 6 aligned float4 loads, front-batched (MLP=6).
    float v[24];
    if (t0 >= N_TAPS) {
        const float4* __restrict__ p =
            reinterpret_cast<const float4*>(xr + t0 - 16);
        #pragma unroll
        for (int i = 0; i < 6; i++) {
            float4 f = p[i];
            v[4*i + 0] = f.x;
            v[4*i + 1] = f.y;
            v[4*i + 2] = f.z;
            v[4*i + 3] = f.w;
        }
    } else {
        // Row head: zero-padded shift register. Only 2 threads/row (t0=0,8).
        #pragma unroll
        for (int i = 0; i < 24; i++) {
            int idx = t0 - 16 + i;
            v[i] = (idx >= 0) ? xr[idx] : 0.0f;
        }
    }

    // y[t0+j] = sum_k c_taps[k] * v[16 + j - k]; taps via LDCU/uniform.
    float acc[OUTS_PER_THREAD];
    #pragma unroll
    for (int j = 0; j < OUTS_PER_THREAD; j++) {
        float a = 0.0f;
        #pragma unroll
        for (int k = 0; k < N_TAPS; k++) {
            a = fmaf(c_taps[k], v[16 + j - k], a);
        }
        acc[j] = a;
    }

    float* yr = y + (size_t)row * T_LEN + t0;
    float4 o0, o1;
    o0.x = acc[0]; o0.y = acc[1]; o0.z = acc[2]; o0.w = acc[3];
    o1.x = acc[4]; o1.y = acc[5]; o1.z = acc[6]; o1.w = acc[7];
    // Streaming stores: y is never re-read; keep it out of x's L2 space.
    __stcs(reinterpret_cast<float4*>(yr) + 0, o0);
    __stcs(reinterpret_cast<float4*>(yr) + 1, o1);
}

extern "C" void kernel_launch(void* const* d_in, const int* in_sizes, int n_in,
                              void* d_out, int out_size)
{
    const float* x = (const float*)d_in[0];
    const float* b = (const float*)d_in[1];
    float* y = (float*)d_out;

    // Taps -> constant bank (64 B D2D async copy; graph-capturable).
    cudaMemcpyToSymbolAsync(c_taps, b, N_TAPS * sizeof(float), 0,
                            cudaMemcpyDeviceToDevice, 0);

    const int threads = 256;
    const int threads_per_row = T_LEN / OUTS_PER_THREAD;          // 60000
    dim3 grid((threads_per_row + threads - 1) / threads, BATCH);  // (235, 64)
    fir_kernel<<<grid, threads>>>(x, y);
}